// round 6
// baseline (speedup 1.0000x reference)
#include <cuda_runtime.h>
#include <math.h>

#define DD 8
#define BB 4096
#define VV 1024
#define KSEL 102
#define ROWS (DD * BB)
#define FULLM 0xFFFFFFFFu

__device__ int g_samples[ROWS];
__device__ unsigned g_done = 0;

static __device__ __forceinline__ unsigned key_of(float x) {
    unsigned u = __float_as_uint(x);
    return (u & 0x80000000u) ? ~u : (u | 0x80000000u);
}
static __device__ __forceinline__ float inv_key(unsigned k) {
    return __uint_as_float((k & 0x80000000u) ? (k & 0x7FFFFFFFu) : ~k);
}

// suffix-scan a 256-bin per-warp histogram; find bin containing rank kk (from top)
static __device__ __forceinline__ void scan_hist(const unsigned* h, int lane, int kk,
                                                 int& bin, int& krem, int& cnt)
{
    unsigned v[8]; unsigned tot = 0;
    #pragma unroll
    for (int i = 0; i < 8; i++) { v[i] = h[lane * 8 + i]; tot += v[i]; }
    unsigned suf = tot;
    #pragma unroll
    for (int off = 1; off < 32; off <<= 1) {
        unsigned t = __shfl_down_sync(FULLM, suf, off);
        if (lane + off < 32) suf += t;
    }
    unsigned tail = suf - tot;               // sum over lanes > lane
    int fi = -1; unsigned fnext = 0, fcnt = 0;
    unsigned run = tail;
    #pragma unroll
    for (int i = 7; i >= 0; i--) {
        unsigned Snext = run;
        run += v[i];
        if ((int)run >= kk && (int)Snext < kk) { fi = i; fnext = Snext; fcnt = v[i]; }
    }
    unsigned bal = __ballot_sync(FULLM, fi >= 0);
    int src = __ffs(bal) - 1;
    bin  = __shfl_sync(FULLM, fi, src) + src * 8;
    krem = kk - (int)__shfl_sync(FULLM, fnext, src);
    cnt  = (int)__shfl_sync(FULLM, fcnt, src);
}

__global__ void __launch_bounds__(256, 4)
decode_fused_kernel(const float* __restrict__ logits,
                    const float* __restrict__ uni,
                    const int*   __restrict__ curv,
                    float*       __restrict__ probs_out,
                    float*       __restrict__ tok_out,
                    int flags)   // bit0: write probs, bit1: write tokens
{
    __shared__ float    sx[8][VV];      // 32 KB: masked logits, then exp values
    __shared__ unsigned hist[8][256];   //  8 KB: per-warp histograms
    __shared__ unsigned s_ticket;

    const int warp = threadIdx.x >> 5;
    const int lane = threadIdx.x & 31;
    const int row  = blockIdx.x * 8 + warp;
    const float* lrow = logits + (size_t)row * VV;
    const float* urow = uni    + (size_t)row * VV;
    const int cv = curv[row];
    unsigned* h = hist[warp];
    float*    sv = sx[warp];

    #pragma unroll
    for (int i = 0; i < 8; i++) h[i * 32 + lane] = 0;
    __syncwarp();

    // ---- pass A: load logits once, mask, smem-store, hist top byte, rowmax ----
    unsigned pp[16];                 // packed 16-bit key prefixes, 2 per register
    unsigned mk = 0;
    #pragma unroll
    for (int i = 0; i < 8; i++) {
        float4 l4 = ((const float4*)lrow)[i * 32 + lane];
        if (i == 0) {
            int g = lane * 4;
            if (g == 0 || g < cv)  l4.x = -INFINITY;   // g==0: index-0 mask
            if (g + 1 < cv)        l4.y = -INFINITY;
            if (g + 2 < cv)        l4.z = -INFINITY;
            if (g + 3 < cv)        l4.w = -INFINITY;
        } else if (cv > i * 128) {                     // uniform per warp; cold path
            int g = i * 128 + lane * 4;
            if (g + 0 < cv) l4.x = -INFINITY;
            if (g + 1 < cv) l4.y = -INFINITY;
            if (g + 2 < cv) l4.z = -INFINITY;
            if (g + 3 < cv) l4.w = -INFINITY;
        }
        unsigned k0 = key_of(l4.x), k1 = key_of(l4.y);
        unsigned k2 = key_of(l4.z), k3 = key_of(l4.w);
        ((float4*)sv)[i * 32 + lane] = l4;             // lane-private slots
        atomicAdd(&h[k0 >> 24], 1u);
        atomicAdd(&h[k1 >> 24], 1u);
        atomicAdd(&h[k2 >> 24], 1u);
        atomicAdd(&h[k3 >> 24], 1u);
        mk = max(mk, max(max(k0, k1), max(k2, k3)));
        pp[2 * i + 0] = (k0 >> 16) | (k1 & 0xFFFF0000u);
        pp[2 * i + 1] = (k2 >> 16) | (k3 & 0xFFFF0000u);
    }
    __syncwarp();
    mk = __reduce_max_sync(FULLM, mk);
    const float rowmax = inv_key(mk);

    // ---- radix scan pass 1 ----
    int b1, kk2, c1;
    scan_hist(h, lane, KSEL, b1, kk2, c1);
    #pragma unroll
    for (int i = 0; i < 8; i++) h[lane * 8 + i] = 0;
    __syncwarp();

    // ---- hist pass 2 from stored prefixes ----
    #pragma unroll
    for (int q = 0; q < 16; q++) {
        unsigned pa = pp[q] & 0xFFFFu;
        unsigned pb = pp[q] >> 16;
        if ((int)(pa >> 8) == b1) atomicAdd(&h[pa & 0xFFu], 1u);
        if ((int)(pb >> 8) == b1) atomicAdd(&h[pb & 0xFFu], 1u);
    }
    __syncwarp();

    int b2, kk3, c2;
    scan_hist(h, lane, kk2, b2, kk3, c2);

    const unsigned P16 = ((unsigned)b1 << 8) | (unsigned)b2;
    unsigned T;
    if (c2 == kk3) {
        T = P16 << 16;                       // whole 16-bit bin kept (fast path)
    } else {
        // exact kth among elements with this 16-bit prefix (smem reloads, masked)
        unsigned cur = 0xFFFFFFFFu;
        int rem = kk3;
        while (rem > 0) {
            unsigned m = 0;
            #pragma unroll
            for (int e = 0; e < 32; e++) {
                unsigned p = (e & 1) ? (pp[e >> 1] >> 16) : (pp[e >> 1] & 0xFFFFu);
                if (p == P16) {
                    int g = (e >> 2) * 128 + lane * 4 + (e & 3);
                    unsigned k = key_of(sv[g]);
                    if (k < cur) m = max(m, k);
                }
            }
            m = __reduce_max_sync(FULLM, m);
            int c = 0;
            #pragma unroll
            for (int e = 0; e < 32; e++) {
                unsigned p = (e & 1) ? (pp[e >> 1] >> 16) : (pp[e >> 1] & 0xFFFFu);
                if (p == P16) {
                    int g = (e >> 2) * 128 + lane * 4 + (e & 3);
                    c += (key_of(sv[g]) == m) ? 1 : 0;
                }
            }
            c = __reduce_add_sync(FULLM, c);
            rem -= c;
            cur = m;
        }
        T = cur;
    }

    // ---- pass C: kept mask + sum-exp; overwrite smem with exp values ----
    float s = 0.0f;
    unsigned km = 0;
    #pragma unroll
    for (int i = 0; i < 8; i++) {
        float4 v4 = ((const float4*)sv)[i * 32 + lane];
        float e0 = 0.f, e1 = 0.f, e2 = 0.f, e3 = 0.f;
        if (key_of(v4.x) >= T) { e0 = __expf(v4.x - rowmax); s += e0; km |= 1u << (i * 4 + 0); }
        if (key_of(v4.y) >= T) { e1 = __expf(v4.y - rowmax); s += e1; km |= 1u << (i * 4 + 1); }
        if (key_of(v4.z) >= T) { e2 = __expf(v4.z - rowmax); s += e2; km |= 1u << (i * 4 + 2); }
        if (key_of(v4.w) >= T) { e3 = __expf(v4.w - rowmax); s += e3; km |= 1u << (i * 4 + 3); }
        ((float4*)sv)[i * 32 + lane] = make_float4(e0, e1, e2, e3);
    }
    #pragma unroll
    for (int off = 16; off > 0; off >>= 1)
        s += __shfl_xor_sync(FULLM, s, off);
    const float logZ = logf(s);
    const float invZ = 1.0f / s;

    // ---- pass D: probs = ex * invZ (streamed from smem) ----
    if (flags & 1) {
        float* prow = probs_out + (size_t)row * VV;
        #pragma unroll
        for (int i = 0; i < 8; i++) {
            float4 e4 = ((const float4*)sv)[i * 32 + lane];
            ((float4*)prow)[i * 32 + lane] =
                make_float4(e4.x * invZ, e4.y * invZ, e4.z * invZ, e4.w * invZ);
        }
    }

    // ---- gumbel-max over kept (ffs loop; L1/L2-hot scalar loads) ----
    float bestv = -INFINITY;
    int   besti = VV;
    unsigned m = km;
    while (m) {
        int e = __ffs(m) - 1;
        m &= m - 1;
        int g = (e >> 2) * 128 + lane * 4 + (e & 3);
        float val = __ldg(lrow + g);
        float uu  = __ldg(urow + g);
        float lp  = (val - rowmax) - logZ;
        float gum = -logf(-logf(uu + 1e-20f) + 1e-20f);
        float sc  = lp + gum;
        if (sc > bestv || (sc == bestv && g < besti)) { bestv = sc; besti = g; }
    }
    #pragma unroll
    for (int off = 16; off > 0; off >>= 1) {
        float ov = __shfl_xor_sync(FULLM, bestv, off);
        int   oi = __shfl_xor_sync(FULLM, besti, off);
        if (ov > bestv || (ov == bestv && oi < besti)) { bestv = ov; besti = oi; }
    }
    if (lane == 0) g_samples[row] = besti;

    // ---- fused tokens tail: last block to finish writes tokens ----
    if (flags & 2) {
        __threadfence();
        __syncthreads();
        if (threadIdx.x == 0) s_ticket = atomicAdd(&g_done, 1u);
        __syncthreads();
        if (s_ticket == gridDim.x - 1) {
            for (int i = threadIdx.x; i < ROWS; i += 256) {
                int b = i >> 3;
                int d = i & 7;
                int s0 = g_samples[b];                // d = 0 sample for stream b
                int sd = g_samples[d * BB + b];
                tok_out[i] = (float)((d == 0 || s0 == 1) ? sd : 0);
            }
            __syncthreads();
            if (threadIdx.x == 0) atomicExch(&g_done, 0u);   // self-reset for replay
        }
    }
}

extern "C" void kernel_launch(void* const* d_in, const int* in_sizes, int n_in,
                              void* d_out, int out_size)
{
    const float* logits = (const float*)d_in[0];
    const float* u      = (const float*)d_in[1];
    const int*   cv     = (const int*)d_in[2];
    float* out = (float*)d_out;

    const long long n_probs  = (long long)DD * BB * VV;
    const long long n_tokens = (long long)BB * DD;

    float* tok_ptr   = nullptr;
    float* probs_ptr = nullptr;
    if ((long long)out_size == n_probs + n_tokens) {
        tok_ptr   = out;
        probs_ptr = out + n_tokens;
    } else if ((long long)out_size == n_probs) {
        probs_ptr = out;
    } else {
        tok_ptr = out;
    }
    int flags = (probs_ptr ? 1 : 0) | (tok_ptr ? 2 : 0);

    decode_fused_kernel<<<ROWS / 8, 256>>>(logits, u, cv, probs_ptr, tok_ptr, flags);
}